// round 4
// baseline (speedup 1.0000x reference)
#include <cuda_runtime.h>

#define NUM_R 725
#define NUM_T 180
#define IMG_N 512
#define NSPLIT 4                 // n-dimension split for wave balance (720 blocks)
#define TB 256                   // threads per block
#define NROWS (IMG_N / NSPLIT)   // 128 sweep rows per block
#define CHUNK 16                 // rows staged in smem per sync (32 KB)

// Scratch (device globals per the allocation-free rule)
__device__ float g_imgT[IMG_N * IMG_N];                 // transposed image
__device__ float g_scratch[NSPLIT * NUM_T * NUM_R];     // partials [sp][t][r]

// ---------------------------------------------------------------------------
// Transpose: g_imgT[a*512 + b] = img[b*512 + a]   (so y-sweep reads rows)
// ---------------------------------------------------------------------------
__global__ void dht_transpose(const float* __restrict__ img) {
    __shared__ float tile[32][33];
    int bx = blockIdx.x * 32, by = blockIdx.y * 32;
    int tx = threadIdx.x, ty = threadIdx.y;
#pragma unroll
    for (int i = 0; i < 32; i += 8)
        tile[ty + i][tx] = img[(by + ty + i) * IMG_N + (bx + tx)];
    __syncthreads();
#pragma unroll
    for (int i = 0; i < 32; i += 8)
        g_imgT[(bx + ty + i) * IMG_N + (by + tx)] = tile[tx][ty + i];
}

// ---------------------------------------------------------------------------
// Main Hough kernel. blockIdx.x = theta, blockIdx.y = n-split.
// Thread tid owns rhos {tid, tid+256, tid+512}: consecutive lanes have
// consecutive rho, so the smem gather stride is ~2 floats (~2-way conflict).
// ---------------------------------------------------------------------------
__global__ __launch_bounds__(TB) void dht_main(const float* __restrict__ img) {
    __shared__ float buf[CHUNK * IMG_N];   // 32 KB row stage

    const int t   = blockIdx.x;
    const int sp  = blockIdx.y;
    const int tid = threadIdx.x;

    // theta = t * f32(pi/180); libdevice cos/sin on the identical f32 theta.
    const float theta = __fmul_rn((float)t, 0.017453292519943295f);
    const float c = cosf(theta);
    const float s = sinf(theta);
    const bool use_x = fabsf(s) >= fabsf(c);

    // x-sweep: y = (rho - n*cos)/sin, sample img[n*512 + y]
    // y-sweep: x = (rho - n*sin)/cos, sample img[x*512 + n] = imgT[n*512 + x]
    const float* __restrict__ src = use_x ? img : g_imgT;
    const float den  = use_x ? s : c;
    const float coef = use_x ? c : s;

    // Correctly-rounded reciprocal seed, hoisted; |den| >= cos(45deg) so safe.
    const float rden = __fdiv_rn(1.0f, den);
    const float nden = -den;

    // rho table: f32 linspace(-diag, diag, 725) exactly as computed upstream.
    const float diag  = __fsqrt_rn(524288.0f);                  // sqrt(2*512^2)
    const float delta = __fdiv_rn(__fadd_rn(diag, diag), 724.0f);
    const float ndiag = -diag;

    const int r0 = tid, r1 = tid + TB, r2 = tid + 2 * TB;
    const float rho0 = (r0 == NUM_R - 1) ? diag : __fadd_rn(ndiag, __fmul_rn((float)r0, delta));
    const float rho1 = (r1 == NUM_R - 1) ? diag : __fadd_rn(ndiag, __fmul_rn((float)r1, delta));
    const float rho2 = (r2 == NUM_R - 1) ? diag : __fadd_rn(ndiag, __fmul_rn((float)r2, delta));

    float acc0 = 0.0f, acc1 = 0.0f, acc2 = 0.0f;

    const int nbase0 = sp * NROWS;

    for (int cb = 0; cb < NROWS; cb += CHUNK) {
        __syncthreads();   // previous chunk fully consumed
        {   // stage CHUNK rows (2048 float4), coalesced
            const float4* __restrict__ g = (const float4*)(src + (size_t)(nbase0 + cb) * IMG_N);
            float4* sb = (float4*)buf;
#pragma unroll
            for (int l = 0; l < (CHUNK * IMG_N / 4) / TB; l++)
                sb[tid + l * TB] = g[tid + l * TB];
        }
        __syncthreads();

#pragma unroll 4
        for (int j = 0; j < CHUNK; j++) {
            const float nf = (float)(nbase0 + cb + j);
            const float nc = __fmul_rn(nf, coef);          // shared across 3 rhos
            const float* __restrict__ row = buf + j * IMG_N;

            // Single-step Markstein division: q = RN(num/den) exactly.
            {
                float num = __fsub_rn(rho0, nc);
                float q0 = __fmul_rn(num, rden);
                float q  = __fmaf_rn(__fmaf_rn(nden, q0, num), rden, q0);
                int yi = __float2int_rn(q);                // round half-even + cast
                float v = row[min(max(yi, 0), IMG_N - 1)];
                if ((unsigned)yi < (unsigned)IMG_N) acc0 = __fadd_rn(acc0, v);
            }
            {
                float num = __fsub_rn(rho1, nc);
                float q0 = __fmul_rn(num, rden);
                float q  = __fmaf_rn(__fmaf_rn(nden, q0, num), rden, q0);
                int yi = __float2int_rn(q);
                float v = row[min(max(yi, 0), IMG_N - 1)];
                if ((unsigned)yi < (unsigned)IMG_N) acc1 = __fadd_rn(acc1, v);
            }
            {
                float num = __fsub_rn(rho2, nc);
                float q0 = __fmul_rn(num, rden);
                float q  = __fmaf_rn(__fmaf_rn(nden, q0, num), rden, q0);
                int yi = __float2int_rn(q);
                float v = row[min(max(yi, 0), IMG_N - 1)];
                if ((unsigned)yi < (unsigned)IMG_N) acc2 = __fadd_rn(acc2, v);
            }
        }
    }

    // Coalesced partial-sum stores: scratch[sp][t][r]
    float* dst = g_scratch + ((size_t)sp * NUM_T + t) * NUM_R;
    if (r0 < NUM_R) dst[r0] = acc0;
    if (r1 < NUM_R) dst[r1] = acc1;
    if (r2 < NUM_R) dst[r2] = acc2;
}

// ---------------------------------------------------------------------------
// Deterministic reduce over NSPLIT partials; out[r*180 + t].
// ---------------------------------------------------------------------------
__global__ void dht_reduce(float* __restrict__ out) {
    int i = blockIdx.x * 256 + threadIdx.x;     // i = t*NUM_R + r
    if (i < NUM_T * NUM_R) {
        float v = g_scratch[i];
#pragma unroll
        for (int sp = 1; sp < NSPLIT; sp++)
            v = __fadd_rn(v, g_scratch[(size_t)sp * NUM_T * NUM_R + i]);
        int t = i / NUM_R;
        int r = i - t * NUM_R;
        out[r * NUM_T + t] = v;
    }
}

// ---------------------------------------------------------------------------
extern "C" void kernel_launch(void* const* d_in, const int* in_sizes, int n_in,
                              void* d_out, int out_size) {
    const float* img = (const float*)d_in[0];
    float* out = (float*)d_out;

    dht_transpose<<<dim3(IMG_N / 32, IMG_N / 32), dim3(32, 8)>>>(img);
    dht_main<<<dim3(NUM_T, NSPLIT), TB>>>(img);
    dht_reduce<<<(NUM_T * NUM_R + 255) / 256, 256>>>(out);
}

// round 6
// speedup vs baseline: 1.1470x; 1.1470x over previous
#include <cuda_runtime.h>

#define NUM_R 725
#define NUM_T 180
#define IMG_N 512
#define NSPLIT 4                 // n-dimension split for wave balance (720 blocks)
#define TB 256                   // threads per block
#define NROWS (IMG_N / NSPLIT)   // 128 sweep rows per block
#define CHUNK 16                 // rows staged in smem per sync
#define ROWSTRIDE 516            // 512 data + 4 pad floats (16B, float4-aligned)

// Scratch (device globals per the allocation-free rule)
__device__ float g_imgT[IMG_N * IMG_N];                 // transposed image
__device__ float g_scratch[NSPLIT * NUM_T * NUM_R];     // partials [sp][t][r]

typedef unsigned long long ull;

// ---- packed f32x2 helpers (Blackwell) --------------------------------------
__device__ __forceinline__ ull pk2(float lo, float hi) {
    ull r; asm("mov.b64 %0, {%1, %2};" : "=l"(r) : "f"(lo), "f"(hi)); return r;
}
__device__ __forceinline__ void upk2(float& lo, float& hi, ull v) {
    asm("mov.b64 {%0, %1}, %2;" : "=f"(lo), "=f"(hi) : "l"(v));
}
__device__ __forceinline__ ull mul2(ull a, ull b) {
    ull d; asm("mul.rn.f32x2 %0, %1, %2;" : "=l"(d) : "l"(a), "l"(b)); return d;
}
__device__ __forceinline__ ull add2(ull a, ull b) {
    ull d; asm("add.rn.f32x2 %0, %1, %2;" : "=l"(d) : "l"(a), "l"(b)); return d;
}
__device__ __forceinline__ ull fma2(ull a, ull b, ull c) {
    ull d; asm("fma.rn.f32x2 %0, %1, %2, %3;" : "=l"(d) : "l"(a), "l"(b), "l"(c)); return d;
}

// ---------------------------------------------------------------------------
// Transpose: g_imgT[a*512 + b] = img[b*512 + a]   (so y-sweep reads rows)
// ---------------------------------------------------------------------------
__global__ void dht_transpose(const float* __restrict__ img) {
    __shared__ float tile[32][33];
    int bx = blockIdx.x * 32, by = blockIdx.y * 32;
    int tx = threadIdx.x, ty = threadIdx.y;
#pragma unroll
    for (int i = 0; i < 32; i += 8)
        tile[ty + i][tx] = img[(by + ty + i) * IMG_N + (bx + tx)];
    __syncthreads();
#pragma unroll
    for (int i = 0; i < 32; i += 8)
        g_imgT[(bx + ty + i) * IMG_N + (by + tx)] = tile[tx][ty + i];
}

// ---------------------------------------------------------------------------
// Main Hough kernel. blockIdx.x = theta, blockIdx.y = n-split.
// Thread tid owns rhos {tid, tid+256, tid+512}; rho0/rho1 packed f32x2.
// Zero-padded smem rows (stride 516, row[512]=0) make OOB gathers free:
//   u = min((unsigned)yi, 512) -> OOB reads the zero slot, unconditional add.
// ---------------------------------------------------------------------------
__global__ __launch_bounds__(TB) void dht_main(const float* __restrict__ img) {
    __shared__ float buf[CHUNK * ROWSTRIDE];   // ~33 KB

    const int t   = blockIdx.x;
    const int sp  = blockIdx.y;
    const int tid = threadIdx.x;

    // theta = t * f32(pi/180); libdevice cos/sin on the identical f32 theta.
    const float theta = __fmul_rn((float)t, 0.017453292519943295f);
    const float c = cosf(theta);
    const float s = sinf(theta);
    const bool use_x = fabsf(s) >= fabsf(c);

    // x-sweep: y = (rho - n*cos)/sin over img rows; y-sweep uses imgT rows.
    const float* __restrict__ src = use_x ? img : g_imgT;
    const float den  = use_x ? s : c;
    const float coef = use_x ? c : s;

    // Correctly-rounded reciprocal seed (|den| >= cos45), hoisted.
    const float rden  = __fdiv_rn(1.0f, den);
    const float nden  = -den;
    const float ncoef = -coef;

    // rho table: f32 linspace(-diag, diag, 725).
    const float diag  = __fsqrt_rn(524288.0f);
    const float delta = __fdiv_rn(__fadd_rn(diag, diag), 724.0f);
    const float ndiag = -diag;

    const int r0 = tid, r1 = tid + TB, r2 = tid + 2 * TB;
    const float rho0 = (r0 == NUM_R - 1) ? diag : __fadd_rn(ndiag, __fmul_rn((float)r0, delta));
    const float rho1 = (r1 == NUM_R - 1) ? diag : __fadd_rn(ndiag, __fmul_rn((float)r1, delta));
    const float rho2 = (r2 == NUM_R - 1) ? diag : __fadd_rn(ndiag, __fmul_rn((float)r2, delta));

    // Hoisted packed constants
    const ull rho01  = pk2(rho0, rho1);
    const ull rden2  = pk2(rden, rden);
    const ull nden2  = pk2(nden, nden);
    const ull ncoef2 = pk2(ncoef, ncoef);
    const ull ones2  = pk2(1.0f, 1.0f);

    const int nbase0 = sp * NROWS;
    ull   nf2 = pk2((float)nbase0, (float)nbase0);
    float nfs = (float)nbase0;

    float acc0 = 0.0f, acc1 = 0.0f, acc2 = 0.0f;

    // Zero the per-row pad slots once (staging never touches them).
    if (tid < CHUNK)
        *(float4*)(buf + tid * ROWSTRIDE + IMG_N) = make_float4(0.f, 0.f, 0.f, 0.f);

    for (int cb = 0; cb < NROWS; cb += CHUNK) {
        __syncthreads();   // pads ready / previous chunk consumed
        {   // stage CHUNK rows (2048 float4), coalesced, into padded rows
            const float4* __restrict__ g = (const float4*)(src + (size_t)(nbase0 + cb) * IMG_N);
#pragma unroll
            for (int l = 0; l < (CHUNK * IMG_N / 4) / TB; l++) {
                int idx = tid + l * TB;        // 0..2047
                int jr  = idx >> 7;            // row 0..15
                int cx  = idx & 127;           // float4 within row
                ((float4*)(buf + jr * ROWSTRIDE))[cx] = g[idx];
            }
        }
        __syncthreads();

#pragma unroll 4
        for (int j = 0; j < CHUNK; j++) {
            const float* __restrict__ row = buf + j * ROWSTRIDE;

            // packed pair (rho0, rho1): num = RN(rho + RN(n * -coef))
            ull nnc2 = mul2(nf2, ncoef2);
            ull num2 = add2(rho01, nnc2);
            ull q02  = mul2(num2, rden2);
            ull e2   = fma2(nden2, q02, num2);
            ull q2   = fma2(e2, rden2, q02);       // = RN(num/den) exactly
            float qa, qb; upk2(qa, qb, q2);

            // scalar rho2
            float nums = __fadd_rn(rho2, __fmul_rn(nfs, ncoef));
            float q0s  = __fmul_rn(nums, rden);
            float qs   = __fmaf_rn(__fmaf_rn(nden, q0s, nums), rden, q0s);

            int y0 = __float2int_rn(qa);
            int y1 = __float2int_rn(qb);
            int y2 = __float2int_rn(qs);
            unsigned u0 = min((unsigned)y0, (unsigned)IMG_N);   // OOB -> pad slot (0.0f)
            unsigned u1 = min((unsigned)y1, (unsigned)IMG_N);
            unsigned u2 = min((unsigned)y2, (unsigned)IMG_N);
            acc0 = __fadd_rn(acc0, row[u0]);
            acc1 = __fadd_rn(acc1, row[u1]);
            acc2 = __fadd_rn(acc2, row[u2]);

            nf2 = add2(nf2, ones2);
            nfs = __fadd_rn(nfs, 1.0f);
        }
    }

    // Coalesced partial-sum stores: scratch[sp][t][r]
    float* dst = g_scratch + ((size_t)sp * NUM_T + t) * NUM_R;
    if (r0 < NUM_R) dst[r0] = acc0;
    if (r1 < NUM_R) dst[r1] = acc1;
    if (r2 < NUM_R) dst[r2] = acc2;
}

// ---------------------------------------------------------------------------
// Deterministic reduce over NSPLIT partials; out[r*180 + t].
// ---------------------------------------------------------------------------
__global__ void dht_reduce(float* __restrict__ out) {
    int i = blockIdx.x * 256 + threadIdx.x;     // i = t*NUM_R + r
    if (i < NUM_T * NUM_R) {
        float v = g_scratch[i];
#pragma unroll
        for (int sp = 1; sp < NSPLIT; sp++)
            v = __fadd_rn(v, g_scratch[(size_t)sp * NUM_T * NUM_R + i]);
        int t = i / NUM_R;
        int r = i - t * NUM_R;
        out[r * NUM_T + t] = v;
    }
}

// ---------------------------------------------------------------------------
extern "C" void kernel_launch(void* const* d_in, const int* in_sizes, int n_in,
                              void* d_out, int out_size) {
    const float* img = (const float*)d_in[0];
    float* out = (float*)d_out;

    dht_transpose<<<dim3(IMG_N / 32, IMG_N / 32), dim3(32, 8)>>>(img);
    dht_main<<<dim3(NUM_T, NSPLIT), TB>>>(img);
    dht_reduce<<<(NUM_T * NUM_R + 255) / 256, 256>>>(out);
}

// round 8
// speedup vs baseline: 1.2089x; 1.0539x over previous
#include <cuda_runtime.h>

#define NUM_R 725
#define NUM_T 180
#define IMG_N 512
#define NSPLIT 4                 // n-dimension split (720 blocks = 1 wave @5/SM)
#define TB 256                   // threads per block
#define NROWS (IMG_N / NSPLIT)   // 128 sweep rows per block
#define CHUNK 8                  // rows per pipeline stage
#define ROWSTRIDE 516            // 512 data + 4 pad floats (16B-aligned)
#define NCHUNK (NROWS / CHUNK)   // 16 stages

// Scratch (device globals per the allocation-free rule)
__device__ float g_imgT[IMG_N * IMG_N];                 // transposed image
__device__ float g_scratch[NSPLIT * NUM_T * NUM_R];     // partials [sp][t][r]

typedef unsigned long long ull;

// ---- packed f32x2 helpers (Blackwell) --------------------------------------
__device__ __forceinline__ ull pk2(float lo, float hi) {
    ull r; asm("mov.b64 %0, {%1, %2};" : "=l"(r) : "f"(lo), "f"(hi)); return r;
}
__device__ __forceinline__ void upk2(float& lo, float& hi, ull v) {
    asm("mov.b64 {%0, %1}, %2;" : "=f"(lo), "=f"(hi) : "l"(v));
}
__device__ __forceinline__ ull mul2(ull a, ull b) {
    ull d; asm("mul.rn.f32x2 %0, %1, %2;" : "=l"(d) : "l"(a), "l"(b)); return d;
}
__device__ __forceinline__ ull add2(ull a, ull b) {
    ull d; asm("add.rn.f32x2 %0, %1, %2;" : "=l"(d) : "l"(a), "l"(b)); return d;
}
__device__ __forceinline__ ull fma2(ull a, ull b, ull c) {
    ull d; asm("fma.rn.f32x2 %0, %1, %2, %3;" : "=l"(d) : "l"(a), "l"(b), "l"(c)); return d;
}

// ---- cp.async helpers ------------------------------------------------------
__device__ __forceinline__ void cpasync16(void* smem, const void* gmem) {
    unsigned sa = (unsigned)__cvta_generic_to_shared(smem);
    asm volatile("cp.async.cg.shared.global [%0], [%1], 16;" :: "r"(sa), "l"(gmem));
}
__device__ __forceinline__ void cpasync_commit() {
    asm volatile("cp.async.commit_group;");
}
template <int N>
__device__ __forceinline__ void cpasync_wait() {
    asm volatile("cp.async.wait_group %0;" :: "n"(N));
}

// ---------------------------------------------------------------------------
// Transpose: g_imgT[a*512 + b] = img[b*512 + a]   (so y-sweep reads rows)
// ---------------------------------------------------------------------------
__global__ void dht_transpose(const float* __restrict__ img) {
    __shared__ float tile[32][33];
    int bx = blockIdx.x * 32, by = blockIdx.y * 32;
    int tx = threadIdx.x, ty = threadIdx.y;
#pragma unroll
    for (int i = 0; i < 32; i += 8)
        tile[ty + i][tx] = img[(by + ty + i) * IMG_N + (bx + tx)];
    __syncthreads();
#pragma unroll
    for (int i = 0; i < 32; i += 8)
        g_imgT[(bx + ty + i) * IMG_N + (by + tx)] = tile[tx][ty + i];
}

// ---------------------------------------------------------------------------
// Main Hough kernel. blockIdx.x = theta, blockIdx.y = n-split.
// Thread tid owns rhos {tid, tid+256, tid+512}; rho0/rho1 packed f32x2.
// Double-buffered cp.async staging overlaps L2 reads with compute.
// Zero-padded smem rows (row[512]=0): OOB index -> min(u,512) -> reads 0.
// ---------------------------------------------------------------------------
__global__ __launch_bounds__(TB, 5) void dht_main(const float* __restrict__ img) {
    __shared__ float buf[2][CHUNK * ROWSTRIDE];   // 33 KB total

    const int t   = blockIdx.x;
    const int sp  = blockIdx.y;
    const int tid = threadIdx.x;

    // theta = t * f32(pi/180); libdevice cos/sin on the identical f32 theta.
    const float theta = __fmul_rn((float)t, 0.017453292519943295f);
    const float c = cosf(theta);
    const float s = sinf(theta);
    const bool use_x = fabsf(s) >= fabsf(c);

    const float* __restrict__ src = use_x ? img : g_imgT;
    const float den  = use_x ? s : c;
    const float coef = use_x ? c : s;

    const float rden  = __fdiv_rn(1.0f, den);   // correctly-rounded seed
    const float nden  = -den;
    const float ncoef = -coef;

    // rho table: f32 linspace(-diag, diag, 725).
    const float diag  = __fsqrt_rn(524288.0f);
    const float delta = __fdiv_rn(__fadd_rn(diag, diag), 724.0f);
    const float ndiag = -diag;

    const int r0 = tid, r1 = tid + TB, r2 = tid + 2 * TB;
    const float rho0 = (r0 == NUM_R - 1) ? diag : __fadd_rn(ndiag, __fmul_rn((float)r0, delta));
    const float rho1 = (r1 == NUM_R - 1) ? diag : __fadd_rn(ndiag, __fmul_rn((float)r1, delta));
    const float rho2 = (r2 == NUM_R - 1) ? diag : __fadd_rn(ndiag, __fmul_rn((float)r2, delta));

    const ull rho01  = pk2(rho0, rho1);
    const ull rden2  = pk2(rden, rden);
    const ull nden2  = pk2(nden, nden);
    const ull ncoef2 = pk2(ncoef, ncoef);
    const ull ones2  = pk2(1.0f, 1.0f);

    const int nbase0 = sp * NROWS;
    ull   nf2 = pk2((float)nbase0, (float)nbase0);
    float nfs = (float)nbase0;

    float acc0 = 0.0f, acc1 = 0.0f, acc2 = 0.0f;

    // Zero the pad slots of both buffers once (cp.async never touches them).
    if (tid < 2 * CHUNK) {
        int b = tid >> 3, j = tid & 7;
        *(float4*)(&buf[b][j * ROWSTRIDE + IMG_N]) = make_float4(0.f, 0.f, 0.f, 0.f);
    }

    // Stage issue helper: CHUNK*512 floats = 1024 float4, 4 per thread.
    const float4* __restrict__ gbase = (const float4*)(src + (size_t)nbase0 * IMG_N);

    // Prologue: prefetch chunk 0 into buffer 0.
    {
        const float4* g = gbase;               // chunk 0
#pragma unroll
        for (int l = 0; l < 4; l++) {
            int idx = tid + l * TB;            // 0..1023
            int jr = idx >> 7, cx = idx & 127;
            cpasync16(&((float4*)(&buf[0][jr * ROWSTRIDE]))[cx], &g[idx]);
        }
        cpasync_commit();
    }

    for (int cb = 0; cb < NCHUNK; cb++) {
        if (cb + 1 < NCHUNK) {                 // prefetch next chunk
            const float4* g = gbase + (size_t)(cb + 1) * CHUNK * (IMG_N / 4);
            float* bnext = buf[(cb + 1) & 1];
#pragma unroll
            for (int l = 0; l < 4; l++) {
                int idx = tid + l * TB;
                int jr = idx >> 7, cx = idx & 127;
                cpasync16(&((float4*)(bnext + jr * ROWSTRIDE))[cx], &g[idx]);
            }
            cpasync_commit();
            cpasync_wait<1>();                 // chunk cb complete
        } else {
            cpasync_wait<0>();
        }
        __syncthreads();                       // data visible to all warps

        const float* __restrict__ bcur = buf[cb & 1];
#pragma unroll 4
        for (int j = 0; j < CHUNK; j++) {
            const float* __restrict__ row = bcur + j * ROWSTRIDE;

            // packed pair (rho0, rho1): num = RN(rho + RN(n * -coef))
            ull nnc2 = mul2(nf2, ncoef2);
            ull num2 = add2(rho01, nnc2);
            ull q02  = mul2(num2, rden2);
            ull e2   = fma2(nden2, q02, num2);
            ull q2   = fma2(e2, rden2, q02);   // = RN(num/den) exactly
            float qa, qb; upk2(qa, qb, q2);

            // scalar rho2
            float nums = __fadd_rn(rho2, __fmul_rn(nfs, ncoef));
            float q0s  = __fmul_rn(nums, rden);
            float qs   = __fmaf_rn(__fmaf_rn(nden, q0s, nums), rden, q0s);

            int y0 = __float2int_rn(qa);
            int y1 = __float2int_rn(qb);
            int y2 = __float2int_rn(qs);
            unsigned u0 = min((unsigned)y0, (unsigned)IMG_N);   // OOB -> pad (0.0f)
            unsigned u1 = min((unsigned)y1, (unsigned)IMG_N);
            unsigned u2 = min((unsigned)y2, (unsigned)IMG_N);
            acc0 = __fadd_rn(acc0, row[u0]);
            acc1 = __fadd_rn(acc1, row[u1]);
            acc2 = __fadd_rn(acc2, row[u2]);

            nf2 = add2(nf2, ones2);
            nfs = __fadd_rn(nfs, 1.0f);
        }
        __syncthreads();                       // compute done before buffer reuse
    }

    // Coalesced partial-sum stores: scratch[sp][t][r]
    float* dst = g_scratch + ((size_t)sp * NUM_T + t) * NUM_R;
    if (r0 < NUM_R) dst[r0] = acc0;
    if (r1 < NUM_R) dst[r1] = acc1;
    if (r2 < NUM_R) dst[r2] = acc2;
}

// ---------------------------------------------------------------------------
// Deterministic reduce over NSPLIT partials; out[r*180 + t].
// ---------------------------------------------------------------------------
__global__ void dht_reduce(float* __restrict__ out) {
    int i = blockIdx.x * 256 + threadIdx.x;     // i = t*NUM_R + r
    if (i < NUM_T * NUM_R) {
        float v = g_scratch[i];
#pragma unroll
        for (int sp = 1; sp < NSPLIT; sp++)
            v = __fadd_rn(v, g_scratch[(size_t)sp * NUM_T * NUM_R + i]);
        int t = i / NUM_R;
        int r = i - t * NUM_R;
        out[r * NUM_T + t] = v;
    }
}

// ---------------------------------------------------------------------------
extern "C" void kernel_launch(void* const* d_in, const int* in_sizes, int n_in,
                              void* d_out, int out_size) {
    const float* img = (const float*)d_in[0];
    float* out = (float*)d_out;

    dht_transpose<<<dim3(IMG_N / 32, IMG_N / 32), dim3(32, 8)>>>(img);
    dht_main<<<dim3(NUM_T, NSPLIT), TB>>>(img);
    dht_reduce<<<(NUM_T * NUM_R + 255) / 256, 256>>>(out);
}

// round 9
// speedup vs baseline: 1.4512x; 1.2004x over previous
#include <cuda_runtime.h>

#define NUM_R 725
#define NUM_T 180
#define IMG_N 512
#define NSPLIT 4                 // n-dimension split (720 blocks = 1 wave @5/SM)
#define TB 256                   // threads per block
#define NROWS (IMG_N / NSPLIT)   // 128 sweep rows per block
#define CHUNK 8                  // rows per pipeline stage
#define ROWSTRIDE 516            // 512 data + 4 pad floats (16B-aligned)
#define NCHUNK (NROWS / CHUNK)   // 16 stages

// Scratch (device globals per the allocation-free rule)
__device__ float g_imgT[IMG_N * IMG_N];                 // transposed image
__device__ float g_scratch[NSPLIT * NUM_T * NUM_R];     // partials [sp][t][r]

typedef unsigned long long ull;

// ---- packed f32x2 helpers (Blackwell) --------------------------------------
__device__ __forceinline__ ull pk2(float lo, float hi) {
    ull r; asm("mov.b64 %0, {%1, %2};" : "=l"(r) : "f"(lo), "f"(hi)); return r;
}
__device__ __forceinline__ void upk2(float& lo, float& hi, ull v) {
    asm("mov.b64 {%0, %1}, %2;" : "=f"(lo), "=f"(hi) : "l"(v));
}
__device__ __forceinline__ ull mul2(ull a, ull b) {
    ull d; asm("mul.rn.f32x2 %0, %1, %2;" : "=l"(d) : "l"(a), "l"(b)); return d;
}
__device__ __forceinline__ ull add2(ull a, ull b) {
    ull d; asm("add.rn.f32x2 %0, %1, %2;" : "=l"(d) : "l"(a), "l"(b)); return d;
}
__device__ __forceinline__ ull fma2(ull a, ull b, ull c) {
    ull d; asm("fma.rn.f32x2 %0, %1, %2, %3;" : "=l"(d) : "l"(a), "l"(b), "l"(c)); return d;
}

// ---- cp.async helpers ------------------------------------------------------
__device__ __forceinline__ void cpasync16(void* smem, const void* gmem) {
    unsigned sa = (unsigned)__cvta_generic_to_shared(smem);
    asm volatile("cp.async.cg.shared.global [%0], [%1], 16;" :: "r"(sa), "l"(gmem));
}
__device__ __forceinline__ void cpasync_commit() {
    asm volatile("cp.async.commit_group;");
}
template <int N>
__device__ __forceinline__ void cpasync_wait() {
    asm volatile("cp.async.wait_group %0;" :: "n"(N));
}

// ---------------------------------------------------------------------------
// Transpose: g_imgT[a*512 + b] = img[b*512 + a]   (so y-sweep reads rows)
// ---------------------------------------------------------------------------
__global__ void dht_transpose(const float* __restrict__ img) {
    __shared__ float tile[32][33];
    int bx = blockIdx.x * 32, by = blockIdx.y * 32;
    int tx = threadIdx.x, ty = threadIdx.y;
#pragma unroll
    for (int i = 0; i < 32; i += 8)
        tile[ty + i][tx] = img[(by + ty + i) * IMG_N + (bx + tx)];
    __syncthreads();
#pragma unroll
    for (int i = 0; i < 32; i += 8)
        g_imgT[(bx + ty + i) * IMG_N + (by + tx)] = tile[tx][ty + i];
}

// ---------------------------------------------------------------------------
// Main Hough kernel. blockIdx.x = theta, blockIdx.y = n-split.
// Warp w owns rhos [96w, 96w+96); lane l handles r = 96w + 32k + l, k=0..2
// (lane stride ~2 words in smem -> ~2-way LDS conflict).
// Warp-uniform 4-corner band test skips whole (warp,chunk) tiles whose
// samples are all out of bounds (they'd add exactly +0.0f).
// Zero-padded smem rows (row[512]=0): OOB index -> min(u,512) -> reads 0.
// ---------------------------------------------------------------------------
__global__ __launch_bounds__(TB, 5) void dht_main(const float* __restrict__ img) {
    __shared__ float buf[2][CHUNK * ROWSTRIDE];   // 33 KB total

    const int t   = blockIdx.x;
    const int sp  = blockIdx.y;
    const int tid = threadIdx.x;
    const int w   = tid >> 5;
    const int ln  = tid & 31;

    // theta = t * f32(pi/180); libdevice cos/sin on the identical f32 theta.
    const float theta = __fmul_rn((float)t, 0.017453292519943295f);
    const float c = cosf(theta);
    const float s = sinf(theta);
    const bool use_x = fabsf(s) >= fabsf(c);

    const float* __restrict__ src = use_x ? img : g_imgT;
    const float den  = use_x ? s : c;
    const float coef = use_x ? c : s;

    const float rden  = __fdiv_rn(1.0f, den);   // correctly-rounded seed
    const float nden  = -den;
    const float ncoef = -coef;

    // rho table: f32 linspace(-diag, diag, 725).
    const float diag  = __fsqrt_rn(524288.0f);
    const float delta = __fdiv_rn(__fadd_rn(diag, diag), 724.0f);
    const float ndiag = -diag;

    const int r0 = 96 * w + ln, r1 = r0 + 32, r2 = r0 + 64;
    const float rho0 = (r0 == NUM_R - 1) ? diag : __fadd_rn(ndiag, __fmul_rn((float)r0, delta));
    const float rho1 = (r1 == NUM_R - 1) ? diag : __fadd_rn(ndiag, __fmul_rn((float)r1, delta));
    const float rho2 = (r2 == NUM_R - 1) ? diag : __fadd_rn(ndiag, __fmul_rn((float)r2, delta));

    const ull rho01  = pk2(rho0, rho1);
    const ull rden2  = pk2(rden, rden);
    const ull nden2  = pk2(nden, nden);
    const ull ncoef2 = pk2(ncoef, ncoef);
    const ull ones2  = pk2(1.0f, 1.0f);

    // Warp-uniform rho bounds for the band test (+/- delta slack).
    const float rhoA = ndiag + ((float)(96 * w) - 1.0f) * delta;
    const float rhoB = ndiag + ((float)(96 * w + 95) + 1.0f) * delta;

    const int nbase0 = sp * NROWS;

    float acc0 = 0.0f, acc1 = 0.0f, acc2 = 0.0f;

    // Zero the pad slots of both buffers once (cp.async never touches them).
    if (tid < 2 * CHUNK) {
        int b = tid >> 3, j = tid & 7;
        *(float4*)(&buf[b][j * ROWSTRIDE + IMG_N]) = make_float4(0.f, 0.f, 0.f, 0.f);
    }

    const float4* __restrict__ gbase = (const float4*)(src + (size_t)nbase0 * IMG_N);

    // Prologue: prefetch chunk 0 into buffer 0.
    {
#pragma unroll
        for (int l = 0; l < 4; l++) {
            int idx = tid + l * TB;            // 0..1023
            int jr = idx >> 7, cx = idx & 127;
            cpasync16(&((float4*)(&buf[0][jr * ROWSTRIDE]))[cx], &gbase[idx]);
        }
        cpasync_commit();
    }

    for (int cb = 0; cb < NCHUNK; cb++) {
        if (cb + 1 < NCHUNK) {                 // prefetch next chunk
            const float4* g = gbase + (size_t)(cb + 1) * CHUNK * (IMG_N / 4);
            float* bnext = buf[(cb + 1) & 1];
#pragma unroll
            for (int l = 0; l < 4; l++) {
                int idx = tid + l * TB;
                int jr = idx >> 7, cx = idx & 127;
                cpasync16(&((float4*)(bnext + jr * ROWSTRIDE))[cx], &g[idx]);
            }
            cpasync_commit();
            cpasync_wait<1>();                 // chunk cb complete
        } else {
            cpasync_wait<0>();
        }
        __syncthreads();                       // data visible to all warps

        // ---- warp-uniform band test: can any sample in this tile land? ----
        const float n0f = (float)(nbase0 + cb * CHUNK);
        const float n1f = n0f + (float)(CHUNK - 1);
        float y00 = (rhoA - n0f * coef) * rden;
        float y01 = (rhoA - n1f * coef) * rden;
        float y10 = (rhoB - n0f * coef) * rden;
        float y11 = (rhoB - n1f * coef) * rden;
        float ymin = fminf(fminf(y00, y01), fminf(y10, y11));
        float ymax = fmaxf(fmaxf(y00, y01), fmaxf(y10, y11));

        if (ymax >= -4.0f && ymin <= (float)IMG_N + 4.0f) {
            const float* __restrict__ bcur = buf[cb & 1];
            ull nf2 = pk2(n0f, n0f);
#pragma unroll 4
            for (int j = 0; j < CHUNK; j++) {
                const float* __restrict__ row = bcur + j * ROWSTRIDE;

                // packed pair (rho0, rho1): num = RN(rho + RN(n * -coef))
                ull nnc2 = mul2(nf2, ncoef2);
                float nncs, nnch; upk2(nncs, nnch, nnc2);   // lo = n*(-coef)
                ull num2 = add2(rho01, nnc2);
                ull q02  = mul2(num2, rden2);
                ull e2   = fma2(nden2, q02, num2);
                ull q2   = fma2(e2, rden2, q02);   // = RN(num/den) exactly
                float qa, qb; upk2(qa, qb, q2);

                // scalar rho2 (reuses packed n*(-coef) product)
                float nums = __fadd_rn(rho2, nncs);
                float q0s  = __fmul_rn(nums, rden);
                float qs   = __fmaf_rn(__fmaf_rn(nden, q0s, nums), rden, q0s);

                int y0 = __float2int_rn(qa);
                int y1 = __float2int_rn(qb);
                int y2 = __float2int_rn(qs);
                unsigned u0 = min((unsigned)y0, (unsigned)IMG_N);  // OOB -> pad (0.0f)
                unsigned u1 = min((unsigned)y1, (unsigned)IMG_N);
                unsigned u2 = min((unsigned)y2, (unsigned)IMG_N);
                acc0 = __fadd_rn(acc0, row[u0]);
                acc1 = __fadd_rn(acc1, row[u1]);
                acc2 = __fadd_rn(acc2, row[u2]);

                nf2 = add2(nf2, ones2);
            }
        }
        __syncthreads();                       // compute done before buffer reuse
    }

    // Partial-sum stores: scratch[sp][t][r]; each k-group is a coalesced
    // 32-wide segment. r0 < 725 always; guard r1/r2.
    float* dst = g_scratch + ((size_t)sp * NUM_T + t) * NUM_R;
    dst[r0] = acc0;
    if (r1 < NUM_R) dst[r1] = acc1;
    if (r2 < NUM_R) dst[r2] = acc2;
}

// ---------------------------------------------------------------------------
// Deterministic reduce over NSPLIT partials; out[r*180 + t].
// ---------------------------------------------------------------------------
__global__ void dht_reduce(float* __restrict__ out) {
    int i = blockIdx.x * 256 + threadIdx.x;     // i = t*NUM_R + r
    if (i < NUM_T * NUM_R) {
        float v = g_scratch[i];
#pragma unroll
        for (int sp = 1; sp < NSPLIT; sp++)
            v = __fadd_rn(v, g_scratch[(size_t)sp * NUM_T * NUM_R + i]);
        int t = i / NUM_R;
        int r = i - t * NUM_R;
        out[r * NUM_T + t] = v;
    }
}

// ---------------------------------------------------------------------------
extern "C" void kernel_launch(void* const* d_in, const int* in_sizes, int n_in,
                              void* d_out, int out_size) {
    const float* img = (const float*)d_in[0];
    float* out = (float*)d_out;

    dht_transpose<<<dim3(IMG_N / 32, IMG_N / 32), dim3(32, 8)>>>(img);
    dht_main<<<dim3(NUM_T, NSPLIT), TB>>>(img);
    dht_reduce<<<(NUM_T * NUM_R + 255) / 256, 256>>>(out);
}